// round 1
// baseline (speedup 1.0000x reference)
#include <cuda_runtime.h>
#include <cuda_bf16.h>
#include <math.h>

#define EPSV 1e-5f
#define NNODES 100000
#define DIM 256

// ---------------- scratch (device globals; no runtime allocation) ----------
__device__ float g_z[(size_t)NNODES * DIM];     // x @ kernel
__device__ float g_htan[(size_t)NNODES * DIM];  // tangent-space features
__device__ float g_bhyp[DIM];                   // exp_map_0(bias)
__device__ float g_scal[4];                     // c, sqrt_c, ||b_hyp||^2

// ---------------- prep: c = softplus(c_theta), b_hyp, ||b_hyp||^2 ----------
__global__ void prep_kernel(const float* __restrict__ bias,
                            const float* __restrict__ c_theta) {
    __shared__ float red[256];
    int tid = threadIdx.x;
    float b = bias[tid];
    red[tid] = b * b;
    __syncthreads();
    for (int s = 128; s > 0; s >>= 1) {
        if (tid < s) red[tid] += red[tid + s];
        __syncthreads();
    }
    float bb_bias = red[0];

    float ct = c_theta[0];
    float c  = log1pf(expf(ct));        // softplus
    float sc = sqrtf(c);

    float n  = fmaxf(sqrtf(bb_bias), EPSV);
    float f  = tanhf(sc * n) / (sc * n);
    g_bhyp[tid] = f * b;
    if (tid == 0) {
        g_scal[0] = c;
        g_scal[1] = sc;
        g_scal[2] = f * f * bb_bias;    // ||b_hyp||^2
    }
}

// ---------------- SGEMM: z = x[N,256] @ W[256,256] -------------------------
// 128x128 tile, BK=16, 256 threads, 8x8 microtile per thread.
__global__ __launch_bounds__(256) void gemm_kernel(const float* __restrict__ X,
                                                   const float* __restrict__ W,
                                                   float* __restrict__ Z,
                                                   int nrows) {
    __shared__ float As[16][128];   // transposed: As[k][m]
    __shared__ float Bs[16][128];   // Bs[k][n]

    const int tid = threadIdx.x;
    const int tx = tid & 15;        // 0..15 -> N
    const int ty = tid >> 4;        // 0..15 -> M
    const int rowBase = blockIdx.y * 128;
    const int colBase = blockIdx.x * 128;

    float acc[8][8];
#pragma unroll
    for (int i = 0; i < 8; i++)
#pragma unroll
        for (int j = 0; j < 8; j++) acc[i][j] = 0.0f;

#pragma unroll 1
    for (int k0 = 0; k0 < 256; k0 += 16) {
        // load A tile: 128 rows x 16 k  (512 float4, 2 per thread)
#pragma unroll
        for (int i = 0; i < 2; i++) {
            int idx = tid + i * 256;          // 0..511
            int r   = idx >> 2;               // 0..127
            int q   = idx & 3;                // which float4 along k
            int grow = rowBase + r;
            float4 v = make_float4(0.f, 0.f, 0.f, 0.f);
            if (grow < nrows)
                v = *reinterpret_cast<const float4*>(X + (size_t)grow * 256 + k0 + q * 4);
            As[q * 4 + 0][r] = v.x;
            As[q * 4 + 1][r] = v.y;
            As[q * 4 + 2][r] = v.z;
            As[q * 4 + 3][r] = v.w;
        }
        // load B tile: 16 k x 128 cols (512 float4, 2 per thread)
#pragma unroll
        for (int i = 0; i < 2; i++) {
            int idx = tid + i * 256;
            int kr  = idx >> 5;               // 0..15
            int cq  = idx & 31;               // 0..31 float4 along n
            float4 v = *reinterpret_cast<const float4*>(W + (size_t)(k0 + kr) * 256 + colBase + cq * 4);
            *reinterpret_cast<float4*>(&Bs[kr][cq * 4]) = v;
        }
        __syncthreads();

#pragma unroll
        for (int k = 0; k < 16; k++) {
            float a[8], b[8];
            float4 a0 = *reinterpret_cast<const float4*>(&As[k][ty * 8]);
            float4 a1 = *reinterpret_cast<const float4*>(&As[k][ty * 8 + 4]);
            float4 b0 = *reinterpret_cast<const float4*>(&Bs[k][tx * 8]);
            float4 b1 = *reinterpret_cast<const float4*>(&Bs[k][tx * 8 + 4]);
            a[0]=a0.x; a[1]=a0.y; a[2]=a0.z; a[3]=a0.w;
            a[4]=a1.x; a[5]=a1.y; a[6]=a1.z; a[7]=a1.w;
            b[0]=b0.x; b[1]=b0.y; b[2]=b0.z; b[3]=b0.w;
            b[4]=b1.x; b[5]=b1.y; b[6]=b1.z; b[7]=b1.w;
#pragma unroll
            for (int i = 0; i < 8; i++)
#pragma unroll
                for (int j = 0; j < 8; j++)
                    acc[i][j] = fmaf(a[i], b[j], acc[i][j]);
        }
        __syncthreads();
    }

    // store
#pragma unroll
    for (int i = 0; i < 8; i++) {
        int row = rowBase + ty * 8 + i;
        if (row < nrows) {
            float4 v0 = make_float4(acc[i][0], acc[i][1], acc[i][2], acc[i][3]);
            float4 v1 = make_float4(acc[i][4], acc[i][5], acc[i][6], acc[i][7]);
            *reinterpret_cast<float4*>(Z + (size_t)row * 256 + colBase + tx * 8)     = v0;
            *reinterpret_cast<float4*>(Z + (size_t)row * 256 + colBase + tx * 8 + 4) = v1;
        }
    }
}

// ---------------- hyperbolic pointwise: z -> h_tan  (one warp per row) -----
__global__ __launch_bounds__(256) void pointwise_kernel(const float* __restrict__ Z,
                                                        float* __restrict__ HT,
                                                        int nrows) {
    int gwarp = (blockIdx.x * blockDim.x + threadIdx.x) >> 5;
    int lane  = threadIdx.x & 31;
    if (gwarp >= nrows) return;

    const float* zrow = Z + (size_t)gwarp * 256;
    float4 z0 = *reinterpret_cast<const float4*>(zrow + lane * 4);
    float4 z1 = *reinterpret_cast<const float4*>(zrow + lane * 4 + 128);
    float4 b0 = *reinterpret_cast<const float4*>(g_bhyp + lane * 4);
    float4 b1 = *reinterpret_cast<const float4*>(g_bhyp + lane * 4 + 128);

    float zz = z0.x*z0.x + z0.y*z0.y + z0.z*z0.z + z0.w*z0.w
             + z1.x*z1.x + z1.y*z1.y + z1.z*z1.z + z1.w*z1.w;
    float zb = z0.x*b0.x + z0.y*b0.y + z0.z*b0.z + z0.w*b0.w
             + z1.x*b1.x + z1.y*b1.y + z1.z*b1.z + z1.w*b1.w;
#pragma unroll
    for (int off = 16; off > 0; off >>= 1) {
        zz += __shfl_xor_sync(0xFFFFFFFFu, zz, off);
        zb += __shfl_xor_sync(0xFFFFFFFFu, zb, off);
    }

    float c   = g_scal[0];
    float sc  = g_scal[1];
    float bbh = g_scal[2];

    // exp_map_0(z)
    float nz = fmaxf(sqrtf(zz), EPSV);
    float f1 = tanhf(sc * nz) / (sc * nz);

    float ab = f1 * zb;          // <z_hyp, b_hyp>
    float aa = f1 * f1 * zz;     // ||z_hyp||^2

    // mobius add (coefficients only)
    float t     = 1.0f + 2.0f * c * ab;
    float alpha = t + c * bbh;
    float beta  = 1.0f - c * aa;
    float den   = fmaxf(t + c * c * aa * bbh, EPSV);

    // ||h||^2 from scalars
    float hh = (alpha * alpha * aa + 2.0f * alpha * beta * ab + beta * beta * bbh)
               / (den * den);

    // project
    float npr   = fmaxf(sqrtf(hh), EPSV);
    float maxn  = (1.0f - EPSV) / sc;
    float scale = (npr > maxn) ? (maxn / npr) : 1.0f;

    // log_map_0
    float ny  = fmaxf(scale * sqrtf(hh), EPSV);
    float arg = fminf(sc * ny, 1.0f - EPSV);
    float fac = atanhf(arg) / (sc * ny);

    float cA = fac * scale * alpha * f1 / den;   // multiplies z
    float cB = fac * scale * beta / den;         // multiplies b_hyp

    float4 o0 = make_float4(cA*z0.x + cB*b0.x, cA*z0.y + cB*b0.y,
                            cA*z0.z + cB*b0.z, cA*z0.w + cB*b0.w);
    float4 o1 = make_float4(cA*z1.x + cB*b1.x, cA*z1.y + cB*b1.y,
                            cA*z1.z + cB*b1.z, cA*z1.w + cB*b1.w);
    float* orow = HT + (size_t)gwarp * 256;
    *reinterpret_cast<float4*>(orow + lane * 4)       = o0;
    *reinterpret_cast<float4*>(orow + lane * 4 + 128) = o1;
}

// ---------------- zero output ----------------------------------------------
__global__ void zero_kernel(float4* __restrict__ out, int n4) {
    int i = blockIdx.x * blockDim.x + threadIdx.x;
    if (i < n4) out[i] = make_float4(0.f, 0.f, 0.f, 0.f);
}

// ---------------- edge scatter with vectorized reductions ------------------
__device__ __forceinline__ void red_add_v4(float* p, float4 v) {
    asm volatile("red.global.add.v4.f32 [%0], {%1, %2, %3, %4};"
                 :: "l"(p), "f"(v.x), "f"(v.y), "f"(v.z), "f"(v.w)
                 : "memory");
}

__global__ __launch_bounds__(256) void scatter_kernel(const int* __restrict__ rows,
                                                      const int* __restrict__ cols,
                                                      const float* __restrict__ vals,
                                                      const float* __restrict__ HT,
                                                      float* __restrict__ out,
                                                      int nE) {
    int gwarp = (blockIdx.x * blockDim.x + threadIdx.x) >> 5;
    int lane  = threadIdx.x & 31;
    int nWarps = (gridDim.x * blockDim.x) >> 5;

    for (int e = gwarp; e < nE; e += nWarps) {
        int r = __ldg(rows + e);
        int c = __ldg(cols + e);
        float v = __ldg(vals + e);
        const float* src = HT + (size_t)c * 256;
        float* dst = out + (size_t)r * 256;

        float4 s0 = *reinterpret_cast<const float4*>(src + lane * 4);
        float4 s1 = *reinterpret_cast<const float4*>(src + lane * 4 + 128);
        s0.x *= v; s0.y *= v; s0.z *= v; s0.w *= v;
        s1.x *= v; s1.y *= v; s1.z *= v; s1.w *= v;
        red_add_v4(dst + lane * 4, s0);
        red_add_v4(dst + lane * 4 + 128, s1);
    }
}

// ---------------- in-place relu --------------------------------------------
__global__ void relu_kernel(float4* __restrict__ out, int n4) {
    int i = blockIdx.x * blockDim.x + threadIdx.x;
    if (i < n4) {
        float4 v = out[i];
        v.x = fmaxf(v.x, 0.f);
        v.y = fmaxf(v.y, 0.f);
        v.z = fmaxf(v.z, 0.f);
        v.w = fmaxf(v.w, 0.f);
        out[i] = v;
    }
}

// ---------------- launch ----------------------------------------------------
extern "C" void kernel_launch(void* const* d_in, const int* in_sizes, int n_in,
                              void* d_out, int out_size) {
    const float* x       = (const float*)d_in[0];
    const int*   adjRows = (const int*)  d_in[1];
    const int*   adjCols = (const int*)  d_in[2];
    const float* adjVals = (const float*)d_in[3];
    const float* Wk      = (const float*)d_in[4];
    const float* bias    = (const float*)d_in[5];
    const float* cTheta  = (const float*)d_in[6];
    float* out = (float*)d_out;

    const int nNodes = in_sizes[0] / DIM;   // 100000
    const int nE     = in_sizes[1];         // 3200000
    const int n4     = out_size / 4;        // float4 count

    float* zPtr;    cudaGetSymbolAddress((void**)&zPtr,  g_z);
    float* htPtr;   cudaGetSymbolAddress((void**)&htPtr, g_htan);

    // 1. constants + hyperbolic bias
    prep_kernel<<<1, 256>>>(bias, cTheta);

    // 2. z = x @ W
    dim3 gGrid(2, (nNodes + 127) / 128);
    gemm_kernel<<<gGrid, 256>>>(x, Wk, zPtr, nNodes);

    // 3. hyperbolic pointwise -> h_tan
    int pwBlocks = (nNodes + 7) / 8;        // 8 warps (rows) per block
    pointwise_kernel<<<pwBlocks, 256>>>(zPtr, htPtr, nNodes);

    // 4. zero out
    zero_kernel<<<(n4 + 255) / 256, 256>>>((float4*)out, n4);

    // 5. edge scatter (vec4 global reductions)
    scatter_kernel<<<8192, 256>>>(adjRows, adjCols, adjVals, htPtr, out, nE);

    // 6. relu in place
    relu_kernel<<<(n4 + 255) / 256, 256>>>((float4*)out, n4);
}

// round 4
// speedup vs baseline: 1.9182x; 1.9182x over previous
#include <cuda_runtime.h>
#include <cuda_bf16.h>
#include <math.h>

#define EPSV 1e-5f
#define NNODES 100000
#define NEDGES 3200000
#define DIM 256
#define SCAN_T 1024
#define SCAN_BLOCKS ((NNODES + SCAN_T - 1) / SCAN_T)   // 98

// ---------------- scratch (device globals; no runtime allocation) ----------
__device__ float g_htan[(size_t)NNODES * DIM];   // tangent-space features
__device__ float g_bhyp[DIM];                    // exp_map_0(bias)
__device__ float g_scal[4];                      // c, sqrt_c, ||b_hyp||^2
__device__ int   g_count[NNODES];                // per-row edge counts
__device__ int   g_incl[NNODES];                 // inclusive per-block scans
__device__ int   g_partials[SCAN_BLOCKS];        // block totals
__device__ int   g_partialsEx[SCAN_BLOCKS];      // exclusive-scanned totals
__device__ int   g_rowStart[NNODES + 1];         // CSR row offsets
__device__ int   g_cursor[NNODES];               // fill cursors
__device__ uint2 g_ePacked[NEDGES];              // {col, bits(val)} reordered

// ---------------- prep: c = softplus(c_theta), b_hyp, ||b_hyp||^2 ----------
__global__ void prep_kernel(const float* __restrict__ bias,
                            const float* __restrict__ c_theta) {
    __shared__ float red[256];
    int tid = threadIdx.x;
    float b = bias[tid];
    red[tid] = b * b;
    __syncthreads();
    for (int s = 128; s > 0; s >>= 1) {
        if (tid < s) red[tid] += red[tid + s];
        __syncthreads();
    }
    float bb_bias = red[0];

    float ct = c_theta[0];
    float c  = log1pf(expf(ct));        // softplus
    float sc = sqrtf(c);

    float n  = fmaxf(sqrtf(bb_bias), EPSV);
    float f  = tanhf(sc * n) / (sc * n);
    g_bhyp[tid] = f * b;
    if (tid == 0) {
        g_scal[0] = c;
        g_scal[1] = sc;
        g_scal[2] = f * f * bb_bias;    // ||b_hyp||^2
    }
}

// ---------------- fused SGEMM + hyperbolic pointwise ------------------------
// tile 64 rows x 256 cols, BK=16, 256 threads, 8x8 microtile.
// Each warp owns 8 complete rows -> row norms via warp shuffles, then
// h_tan = cA * z + cB * b_hyp written directly (no intermediate z buffer).
__global__ __launch_bounds__(256, 2) void gemm_fused_kernel(
        const float* __restrict__ X,
        const float* __restrict__ W,
        float* __restrict__ HT,
        int nrows) {
    __shared__ float As[16][64];    // As[k][m]
    __shared__ float Bs[16][256];   // Bs[k][n]

    const int tid = threadIdx.x;
    const int tx = tid & 31;        // 0..31 -> 32 col-groups of 8
    const int ty = tid >> 5;        // 0..7  -> 8 row-groups of 8 (== warp id)
    const int rowBase = blockIdx.x * 64;

    float acc[8][8];
#pragma unroll
    for (int i = 0; i < 8; i++)
#pragma unroll
        for (int j = 0; j < 8; j++) acc[i][j] = 0.0f;

#pragma unroll 1
    for (int k0 = 0; k0 < 256; k0 += 16) {
        // A tile: 64 rows x 16 k = 256 float4, one per thread
        {
            int r = tid >> 2;               // 0..63
            int q = tid & 3;                // float4 along k
            int grow = rowBase + r;
            float4 v = make_float4(0.f, 0.f, 0.f, 0.f);
            if (grow < nrows)
                v = *reinterpret_cast<const float4*>(X + (size_t)grow * 256 + k0 + q * 4);
            As[q * 4 + 0][r] = v.x;
            As[q * 4 + 1][r] = v.y;
            As[q * 4 + 2][r] = v.z;
            As[q * 4 + 3][r] = v.w;
        }
        // B tile: 16 k x 256 cols = 1024 float4, 4 per thread
#pragma unroll
        for (int i = 0; i < 4; i++) {
            int idx = tid + i * 256;        // 0..1023
            int kr  = idx >> 6;             // 0..15
            int cq  = idx & 63;             // float4 along n
            float4 v = *reinterpret_cast<const float4*>(W + (size_t)(k0 + kr) * 256 + cq * 4);
            *reinterpret_cast<float4*>(&Bs[kr][cq * 4]) = v;
        }
        __syncthreads();

#pragma unroll
        for (int k = 0; k < 16; k++) {
            float a[8], b[8];
            float4 a0 = *reinterpret_cast<const float4*>(&As[k][ty * 8]);
            float4 a1 = *reinterpret_cast<const float4*>(&As[k][ty * 8 + 4]);
            float4 b0 = *reinterpret_cast<const float4*>(&Bs[k][tx * 8]);
            float4 b1 = *reinterpret_cast<const float4*>(&Bs[k][tx * 8 + 4]);
            a[0]=a0.x; a[1]=a0.y; a[2]=a0.z; a[3]=a0.w;
            a[4]=a1.x; a[5]=a1.y; a[6]=a1.z; a[7]=a1.w;
            b[0]=b0.x; b[1]=b0.y; b[2]=b0.z; b[3]=b0.w;
            b[4]=b1.x; b[5]=b1.y; b[6]=b1.z; b[7]=b1.w;
#pragma unroll
            for (int i = 0; i < 8; i++)
#pragma unroll
                for (int j = 0; j < 8; j++)
                    acc[i][j] = fmaf(a[i], b[j], acc[i][j]);
        }
        __syncthreads();
    }

    // ---- fused hyperbolic epilogue ----
    float bh[8];
    {
        float4 h0 = *reinterpret_cast<const float4*>(g_bhyp + tx * 8);
        float4 h1 = *reinterpret_cast<const float4*>(g_bhyp + tx * 8 + 4);
        bh[0]=h0.x; bh[1]=h0.y; bh[2]=h0.z; bh[3]=h0.w;
        bh[4]=h1.x; bh[5]=h1.y; bh[6]=h1.z; bh[7]=h1.w;
    }
    float c   = g_scal[0];
    float sc  = g_scal[1];
    float bbh = g_scal[2];

#pragma unroll
    for (int i = 0; i < 8; i++) {
        // per-row partial sums over this lane's 8 cols
        float zz = 0.f, zb = 0.f;
#pragma unroll
        for (int j = 0; j < 8; j++) {
            zz = fmaf(acc[i][j], acc[i][j], zz);
            zb = fmaf(acc[i][j], bh[j], zb);
        }
#pragma unroll
        for (int off = 16; off > 0; off >>= 1) {
            zz += __shfl_xor_sync(0xFFFFFFFFu, zz, off);
            zb += __shfl_xor_sync(0xFFFFFFFFu, zb, off);
        }

        // exp_map_0(z)
        float nz = fmaxf(sqrtf(zz), EPSV);
        float f1 = tanhf(sc * nz) / (sc * nz);

        float ab = f1 * zb;
        float aa = f1 * f1 * zz;

        float t     = 1.0f + 2.0f * c * ab;
        float alpha = t + c * bbh;
        float beta  = 1.0f - c * aa;
        float den   = fmaxf(t + c * c * aa * bbh, EPSV);

        float hh = (alpha * alpha * aa + 2.0f * alpha * beta * ab + beta * beta * bbh)
                   / (den * den);

        float npr   = fmaxf(sqrtf(hh), EPSV);
        float maxn  = (1.0f - EPSV) / sc;
        float scale = (npr > maxn) ? (maxn / npr) : 1.0f;

        float ny  = fmaxf(scale * sqrtf(hh), EPSV);
        float arg = fminf(sc * ny, 1.0f - EPSV);
        float fac = atanhf(arg) / (sc * ny);

        float cA = fac * scale * alpha * f1 / den;
        float cB = fac * scale * beta / den;

        int row = rowBase + ty * 8 + i;
        if (row < nrows) {
            float4 o0 = make_float4(fmaf(cA, acc[i][0], cB * bh[0]),
                                    fmaf(cA, acc[i][1], cB * bh[1]),
                                    fmaf(cA, acc[i][2], cB * bh[2]),
                                    fmaf(cA, acc[i][3], cB * bh[3]));
            float4 o1 = make_float4(fmaf(cA, acc[i][4], cB * bh[4]),
                                    fmaf(cA, acc[i][5], cB * bh[5]),
                                    fmaf(cA, acc[i][6], cB * bh[6]),
                                    fmaf(cA, acc[i][7], cB * bh[7]));
            float* orow = HT + (size_t)row * 256;
            *reinterpret_cast<float4*>(orow + tx * 8)     = o0;
            *reinterpret_cast<float4*>(orow + tx * 8 + 4) = o1;
        }
    }
}

// ---------------- CSR build -------------------------------------------------
__global__ void zero_count_kernel(int n) {
    int i = blockIdx.x * blockDim.x + threadIdx.x;
    if (i < n) g_count[i] = 0;
}

__global__ void hist_kernel(const int* __restrict__ rows, int nE) {
    int e = blockIdx.x * blockDim.x + threadIdx.x;
    if (e < nE) atomicAdd(&g_count[rows[e]], 1);
}

__global__ __launch_bounds__(SCAN_T) void scan1_kernel(int n) {
    __shared__ int s[SCAN_T];
    int t = threadIdx.x;
    int i = blockIdx.x * SCAN_T + t;
    int v = (i < n) ? g_count[i] : 0;
    s[t] = v;
    __syncthreads();
#pragma unroll
    for (int off = 1; off < SCAN_T; off <<= 1) {
        int add = (t >= off) ? s[t - off] : 0;
        __syncthreads();
        s[t] += add;
        __syncthreads();
    }
    if (i < n) g_incl[i] = s[t];
    if (t == SCAN_T - 1) g_partials[blockIdx.x] = s[t];
}

__global__ void scan2_kernel(int nBlocks) {
    if (threadIdx.x == 0 && blockIdx.x == 0) {
        int run = 0;
        for (int b = 0; b < nBlocks; b++) {
            int t = g_partials[b];
            g_partialsEx[b] = run;
            run += t;
        }
    }
}

__global__ void scan3_kernel(int n, int nE) {
    int i = blockIdx.x * blockDim.x + threadIdx.x;
    if (i < n) {
        int excl = g_incl[i] - g_count[i] + g_partialsEx[i >> 10];
        g_rowStart[i] = excl;
        g_cursor[i]   = excl;
    }
    if (i == 0) g_rowStart[n] = nE;
}

__global__ void reorder_kernel(const int* __restrict__ rows,
                               const int* __restrict__ cols,
                               const float* __restrict__ vals,
                               int nE) {
    int e = blockIdx.x * blockDim.x + threadIdx.x;
    if (e < nE) {
        int r = __ldg(rows + e);
        int p = atomicAdd(&g_cursor[r], 1);
        g_ePacked[p] = make_uint2((unsigned)__ldg(cols + e),
                                  __float_as_uint(__ldg(vals + e)));
    }
}

// ---------------- segmented aggregate: one warp per row, fused ReLU ---------
__global__ __launch_bounds__(512) void aggregate_kernel(const float* __restrict__ HT,
                                                        float* __restrict__ out,
                                                        int nRows) {
    int warp = (blockIdx.x * blockDim.x + threadIdx.x) >> 5;
    int lane = threadIdx.x & 31;
    if (warp >= nRows) return;

    int s    = __ldg(&g_rowStart[warp]);
    int eend = __ldg(&g_rowStart[warp + 1]);

    float4 a0 = make_float4(0.f, 0.f, 0.f, 0.f);
    float4 a1 = make_float4(0.f, 0.f, 0.f, 0.f);

    const float4* HT4 = reinterpret_cast<const float4*>(HT);

    int e = s;
    // 4-edge unrolled main loop: batch 8 independent LDG.128 before any FMA
    for (; e + 4 <= eend; e += 4) {
        uint2 p0 = __ldg(&g_ePacked[e]);
        uint2 p1 = __ldg(&g_ePacked[e + 1]);
        uint2 p2 = __ldg(&g_ePacked[e + 2]);
        uint2 p3 = __ldg(&g_ePacked[e + 3]);
        const float4* r0 = HT4 + (size_t)p0.x * 64;
        const float4* r1 = HT4 + (size_t)p1.x * 64;
        const float4* r2 = HT4 + (size_t)p2.x * 64;
        const float4* r3 = HT4 + (size_t)p3.x * 64;
        float4 x0a = __ldg(&r0[lane]);
        float4 x1a = __ldg(&r1[lane]);
        float4 x2a = __ldg(&r2[lane]);
        float4 x3a = __ldg(&r3[lane]);
        float4 x0b = __ldg(&r0[lane + 32]);
        float4 x1b = __ldg(&r1[lane + 32]);
        float4 x2b = __ldg(&r2[lane + 32]);
        float4 x3b = __ldg(&r3[lane + 32]);
        float v0 = __uint_as_float(p0.y);
        float v1 = __uint_as_float(p1.y);
        float v2 = __uint_as_float(p2.y);
        float v3 = __uint_as_float(p3.y);
        a0.x = fmaf(v0, x0a.x, a0.x); a0.y = fmaf(v0, x0a.y, a0.y);
        a0.z = fmaf(v0, x0a.z, a0.z); a0.w = fmaf(v0, x0a.w, a0.w);
        a1.x = fmaf(v0, x0b.x, a1.x); a1.y = fmaf(v0, x0b.y, a1.y);
        a1.z = fmaf(v0, x0b.z, a1.z); a1.w = fmaf(v0, x0b.w, a1.w);
        a0.x = fmaf(v1, x1a.x, a0.x); a0.y = fmaf(v1, x1a.y, a0.y);
        a0.z = fmaf(v1, x1a.z, a0.z); a0.w = fmaf(v1, x1a.w, a0.w);
        a1.x = fmaf(v1, x1b.x, a1.x); a1.y = fmaf(v1, x1b.y, a1.y);
        a1.z = fmaf(v1, x1b.z, a1.z); a1.w = fmaf(v1, x1b.w, a1.w);
        a0.x = fmaf(v2, x2a.x, a0.x); a0.y = fmaf(v2, x2a.y, a0.y);
        a0.z = fmaf(v2, x2a.z, a0.z); a0.w = fmaf(v2, x2a.w, a0.w);
        a1.x = fmaf(v2, x2b.x, a1.x); a1.y = fmaf(v2, x2b.y, a1.y);
        a1.z = fmaf(v2, x2b.z, a1.z); a1.w = fmaf(v2, x2b.w, a1.w);
        a0.x = fmaf(v3, x3a.x, a0.x); a0.y = fmaf(v3, x3a.y, a0.y);
        a0.z = fmaf(v3, x3a.z, a0.z); a0.w = fmaf(v3, x3a.w, a0.w);
        a1.x = fmaf(v3, x3b.x, a1.x); a1.y = fmaf(v3, x3b.y, a1.y);
        a1.z = fmaf(v3, x3b.z, a1.z); a1.w = fmaf(v3, x3b.w, a1.w);
    }
    for (; e < eend; e++) {
        uint2 p0 = __ldg(&g_ePacked[e]);
        const float4* r0 = HT4 + (size_t)p0.x * 64;
        float4 x0 = __ldg(&r0[lane]);
        float4 x1 = __ldg(&r0[lane + 32]);
        float v0 = __uint_as_float(p0.y);
        a0.x = fmaf(v0, x0.x, a0.x); a0.y = fmaf(v0, x0.y, a0.y);
        a0.z = fmaf(v0, x0.z, a0.z); a0.w = fmaf(v0, x0.w, a0.w);
        a1.x = fmaf(v0, x1.x, a1.x); a1.y = fmaf(v0, x1.y, a1.y);
        a1.z = fmaf(v0, x1.z, a1.z); a1.w = fmaf(v0, x1.w, a1.w);
    }

    // fused ReLU + store (also handles zero-degree rows -> zeros)
    a0.x = fmaxf(a0.x, 0.f); a0.y = fmaxf(a0.y, 0.f);
    a0.z = fmaxf(a0.z, 0.f); a0.w = fmaxf(a0.w, 0.f);
    a1.x = fmaxf(a1.x, 0.f); a1.y = fmaxf(a1.y, 0.f);
    a1.z = fmaxf(a1.z, 0.f); a1.w = fmaxf(a1.w, 0.f);

    float4* out4 = reinterpret_cast<float4*>(out);
    out4[(size_t)warp * 64 + lane]      = a0;
    out4[(size_t)warp * 64 + lane + 32] = a1;
}

// ---------------- launch ----------------------------------------------------
extern "C" void kernel_launch(void* const* d_in, const int* in_sizes, int n_in,
                              void* d_out, int out_size) {
    const float* x       = (const float*)d_in[0];
    const int*   adjRows = (const int*)  d_in[1];
    const int*   adjCols = (const int*)  d_in[2];
    const float* adjVals = (const float*)d_in[3];
    const float* Wk      = (const float*)d_in[4];
    const float* bias    = (const float*)d_in[5];
    const float* cTheta  = (const float*)d_in[6];
    float* out = (float*)d_out;

    const int nNodes = in_sizes[0] / DIM;   // 100000
    const int nE     = in_sizes[1];         // 3200000

    float* htPtr;   cudaGetSymbolAddress((void**)&htPtr, g_htan);

    // constants + hyperbolic bias
    prep_kernel<<<1, 256>>>(bias, cTheta);

    // CSR build (independent of GEMM; single stream serializes fine)
    zero_count_kernel<<<(nNodes + 255) / 256, 256>>>(nNodes);
    hist_kernel<<<(nE + 255) / 256, 256>>>(adjRows, nE);
    scan1_kernel<<<(nNodes + SCAN_T - 1) / SCAN_T, SCAN_T>>>(nNodes);
    scan2_kernel<<<1, 32>>>((nNodes + SCAN_T - 1) / SCAN_T);
    scan3_kernel<<<(nNodes + 255) / 256, 256>>>(nNodes, nE);
    reorder_kernel<<<(nE + 255) / 256, 256>>>(adjRows, adjCols, adjVals, nE);

    // fused GEMM + hyperbolic pointwise -> h_tan
    gemm_fused_kernel<<<(nNodes + 63) / 64, 256>>>(x, Wk, htPtr, nNodes);

    // segmented gather-aggregate with fused ReLU
    aggregate_kernel<<<(nNodes * 32 + 511) / 512, 512>>>(htPtr, out, nNodes);
}

// round 5
// speedup vs baseline: 2.0516x; 1.0695x over previous
#include <cuda_runtime.h>
#include <cuda_bf16.h>
#include <math.h>

#define EPSV 1e-5f
#define NNODES 100000
#define NEDGES 3200000
#define DIM 256
#define SCAN_T 1024
#define SCAN_BLOCKS ((NNODES + SCAN_T - 1) / SCAN_T)   // 98

// ---------------- scratch (device globals; no runtime allocation) ----------
__device__ float g_htan[(size_t)NNODES * DIM];   // tangent-space features
__device__ float g_bhyp[DIM];                    // exp_map_0(bias)
__device__ float g_scal[4];                      // c, sqrt_c, ||b_hyp||^2
__device__ int   g_count[NNODES];                // per-row edge counts
__device__ int   g_incl[NNODES];                 // inclusive per-block scans
__device__ int   g_partials[SCAN_BLOCKS];        // block totals
__device__ int   g_partialsEx[SCAN_BLOCKS];      // exclusive-scanned totals
__device__ int   g_rowStart[NNODES + 1];         // CSR row offsets
__device__ int   g_cursor[NNODES];               // fill cursors
__device__ uint2 g_ePacked[NEDGES];              // {col, bits(val)} reordered

// packed f32x2 FMA: d = a*b + d  (each half is exact fp32 FMA)
#define FMA2(d, a, b) \
    asm("fma.rn.f32x2 %0, %1, %2, %0;" : "+l"(d) : "l"(a), "l"(b))
#define PACK_DUP(d, x) \
    asm("mov.b64 %0, {%1, %1};" : "=l"(d) : "r"(x))
#define UNPACK2(lo, hi, in) \
    asm("mov.b64 {%0, %1}, %2;" : "=f"(lo), "=f"(hi) : "l"(in))

// ---------------- prep: c = softplus(c_theta), b_hyp, ||b_hyp||^2 ----------
__global__ void prep_kernel(const float* __restrict__ bias,
                            const float* __restrict__ c_theta) {
    __shared__ float red[256];
    int tid = threadIdx.x;
    float b = bias[tid];
    red[tid] = b * b;
    __syncthreads();
    for (int s = 128; s > 0; s >>= 1) {
        if (tid < s) red[tid] += red[tid + s];
        __syncthreads();
    }
    float bb_bias = red[0];

    float ct = c_theta[0];
    float c  = log1pf(expf(ct));        // softplus
    float sc = sqrtf(c);

    float n  = fmaxf(sqrtf(bb_bias), EPSV);
    float f  = tanhf(sc * n) / (sc * n);
    g_bhyp[tid] = f * b;
    if (tid == 0) {
        g_scal[0] = c;
        g_scal[1] = sc;
        g_scal[2] = f * f * bb_bias;    // ||b_hyp||^2
    }
}

// ---------------- fused SGEMM + hyperbolic pointwise ------------------------
// tile 64 rows x 256 cols, BK=16, 256 threads, 8x8 microtile.
// Inner product via packed fma.rn.f32x2 (column pairs), double-buffered smem.
__global__ __launch_bounds__(256, 2) void gemm_fused_kernel(
        const float* __restrict__ X,
        const float* __restrict__ W,
        float* __restrict__ HT,
        int nrows) {
    __shared__ __align__(16) float As[2][16][64];    // As[buf][k][m]
    __shared__ __align__(16) float Bs[2][16][256];   // Bs[buf][k][n]

    const int tid = threadIdx.x;
    const int tx = tid & 31;        // 0..31 -> 32 col-groups of 8
    const int ty = tid >> 5;        // 0..7  -> 8 row-groups of 8 (== warp id)
    const int rowBase = blockIdx.x * 64;

    // A-load indices: one float4 per thread
    const int ar = tid >> 2;        // 0..63 row within tile
    const int aq = tid & 3;         // float4 slot along k
    const int agrow = rowBase + ar;

    // packed accumulators: 8 rows x 4 column-pairs
    unsigned long long acc2[8][4];
#pragma unroll
    for (int i = 0; i < 8; i++)
#pragma unroll
        for (int p = 0; p < 4; p++) acc2[i][p] = 0ull;

    // ---- preload tile 0 ----
    {
        float4 va = make_float4(0.f, 0.f, 0.f, 0.f);
        if (agrow < nrows)
            va = *reinterpret_cast<const float4*>(X + (size_t)agrow * 256 + aq * 4);
        As[0][aq * 4 + 0][ar] = va.x;
        As[0][aq * 4 + 1][ar] = va.y;
        As[0][aq * 4 + 2][ar] = va.z;
        As[0][aq * 4 + 3][ar] = va.w;
#pragma unroll
        for (int i = 0; i < 4; i++) {
            int idx = tid + i * 256;
            int kr  = idx >> 6;
            int cq  = idx & 63;
            float4 v = *reinterpret_cast<const float4*>(W + (size_t)kr * 256 + cq * 4);
            *reinterpret_cast<float4*>(&Bs[0][kr][cq * 4]) = v;
        }
    }
    __syncthreads();

#pragma unroll 1
    for (int t = 0; t < 16; t++) {
        const int cur = t & 1;
        const int nxt = cur ^ 1;

        // prefetch next tile into registers
        float4 na = make_float4(0.f, 0.f, 0.f, 0.f);
        float4 nb[4];
        if (t < 15) {
            int k0n = (t + 1) * 16;
            if (agrow < nrows)
                na = *reinterpret_cast<const float4*>(X + (size_t)agrow * 256 + k0n + aq * 4);
#pragma unroll
            for (int i = 0; i < 4; i++) {
                int idx = tid + i * 256;
                int kr  = idx >> 6;
                int cq  = idx & 63;
                nb[i] = *reinterpret_cast<const float4*>(W + (size_t)(k0n + kr) * 256 + cq * 4);
            }
        }

        // compute on current buffer
#pragma unroll
        for (int k = 0; k < 16; k++) {
            float4 a0 = *reinterpret_cast<const float4*>(&As[cur][k][ty * 8]);
            float4 a1 = *reinterpret_cast<const float4*>(&As[cur][k][ty * 8 + 4]);
            ulonglong2 q0 = *reinterpret_cast<const ulonglong2*>(&Bs[cur][k][tx * 8]);
            ulonglong2 q1 = *reinterpret_cast<const ulonglong2*>(&Bs[cur][k][tx * 8 + 4]);

            float a[8];
            a[0]=a0.x; a[1]=a0.y; a[2]=a0.z; a[3]=a0.w;
            a[4]=a1.x; a[5]=a1.y; a[6]=a1.z; a[7]=a1.w;
#pragma unroll
            for (int i = 0; i < 8; i++) {
                unsigned long long ap;
                PACK_DUP(ap, __float_as_uint(a[i]));
                FMA2(acc2[i][0], ap, q0.x);
                FMA2(acc2[i][1], ap, q0.y);
                FMA2(acc2[i][2], ap, q1.x);
                FMA2(acc2[i][3], ap, q1.y);
            }
        }

        // store prefetched tile
        if (t < 15) {
            As[nxt][aq * 4 + 0][ar] = na.x;
            As[nxt][aq * 4 + 1][ar] = na.y;
            As[nxt][aq * 4 + 2][ar] = na.z;
            As[nxt][aq * 4 + 3][ar] = na.w;
#pragma unroll
            for (int i = 0; i < 4; i++) {
                int idx = tid + i * 256;
                int kr  = idx >> 6;
                int cq  = idx & 63;
                *reinterpret_cast<float4*>(&Bs[nxt][kr][cq * 4]) = nb[i];
            }
        }
        __syncthreads();
    }

    // unpack accumulators
    float acc[8][8];
#pragma unroll
    for (int i = 0; i < 8; i++)
#pragma unroll
        for (int p = 0; p < 4; p++)
            UNPACK2(acc[i][2 * p], acc[i][2 * p + 1], acc2[i][p]);

    // ---- fused hyperbolic epilogue ----
    float bh[8];
    {
        float4 h0 = *reinterpret_cast<const float4*>(g_bhyp + tx * 8);
        float4 h1 = *reinterpret_cast<const float4*>(g_bhyp + tx * 8 + 4);
        bh[0]=h0.x; bh[1]=h0.y; bh[2]=h0.z; bh[3]=h0.w;
        bh[4]=h1.x; bh[5]=h1.y; bh[6]=h1.z; bh[7]=h1.w;
    }
    float c   = g_scal[0];
    float sc  = g_scal[1];
    float bbh = g_scal[2];

#pragma unroll
    for (int i = 0; i < 8; i++) {
        float zz = 0.f, zb = 0.f;
#pragma unroll
        for (int j = 0; j < 8; j++) {
            zz = fmaf(acc[i][j], acc[i][j], zz);
            zb = fmaf(acc[i][j], bh[j], zb);
        }
#pragma unroll
        for (int off = 16; off > 0; off >>= 1) {
            zz += __shfl_xor_sync(0xFFFFFFFFu, zz, off);
            zb += __shfl_xor_sync(0xFFFFFFFFu, zb, off);
        }

        // exp_map_0(z)
        float nz = fmaxf(sqrtf(zz), EPSV);
        float f1 = tanhf(sc * nz) / (sc * nz);

        float ab = f1 * zb;
        float aa = f1 * f1 * zz;

        float t2    = 1.0f + 2.0f * c * ab;
        float alpha = t2 + c * bbh;
        float beta  = 1.0f - c * aa;
        float den   = fmaxf(t2 + c * c * aa * bbh, EPSV);

        float hh = (alpha * alpha * aa + 2.0f * alpha * beta * ab + beta * beta * bbh)
                   / (den * den);

        float npr   = fmaxf(sqrtf(hh), EPSV);
        float maxn  = (1.0f - EPSV) / sc;
        float scale = (npr > maxn) ? (maxn / npr) : 1.0f;

        float ny  = fmaxf(scale * sqrtf(hh), EPSV);
        float arg = fminf(sc * ny, 1.0f - EPSV);
        float fac = atanhf(arg) / (sc * ny);

        float cA = fac * scale * alpha * f1 / den;
        float cB = fac * scale * beta / den;

        int row = rowBase + ty * 8 + i;
        if (row < nrows) {
            float4 o0 = make_float4(fmaf(cA, acc[i][0], cB * bh[0]),
                                    fmaf(cA, acc[i][1], cB * bh[1]),
                                    fmaf(cA, acc[i][2], cB * bh[2]),
                                    fmaf(cA, acc[i][3], cB * bh[3]));
            float4 o1 = make_float4(fmaf(cA, acc[i][4], cB * bh[4]),
                                    fmaf(cA, acc[i][5], cB * bh[5]),
                                    fmaf(cA, acc[i][6], cB * bh[6]),
                                    fmaf(cA, acc[i][7], cB * bh[7]));
            float* orow = HT + (size_t)row * 256;
            *reinterpret_cast<float4*>(orow + tx * 8)     = o0;
            *reinterpret_cast<float4*>(orow + tx * 8 + 4) = o1;
        }
    }
}

// ---------------- CSR build -------------------------------------------------
__global__ void zero_count_kernel(int n) {
    int i = blockIdx.x * blockDim.x + threadIdx.x;
    if (i < n) g_count[i] = 0;
}

__global__ void hist_kernel(const int* __restrict__ rows, int nE) {
    int e = blockIdx.x * blockDim.x + threadIdx.x;
    if (e < nE) atomicAdd(&g_count[rows[e]], 1);
}

__global__ __launch_bounds__(SCAN_T) void scan1_kernel(int n) {
    __shared__ int s[SCAN_T];
    int t = threadIdx.x;
    int i = blockIdx.x * SCAN_T + t;
    int v = (i < n) ? g_count[i] : 0;
    s[t] = v;
    __syncthreads();
#pragma unroll
    for (int off = 1; off < SCAN_T; off <<= 1) {
        int add = (t >= off) ? s[t - off] : 0;
        __syncthreads();
        s[t] += add;
        __syncthreads();
    }
    if (i < n) g_incl[i] = s[t];
    if (t == SCAN_T - 1) g_partials[blockIdx.x] = s[t];
}

__global__ void scan2_kernel(int nBlocks) {
    if (threadIdx.x == 0 && blockIdx.x == 0) {
        int run = 0;
        for (int b = 0; b < nBlocks; b++) {
            int t = g_partials[b];
            g_partialsEx[b] = run;
            run += t;
        }
    }
}

__global__ void scan3_kernel(int n, int nE) {
    int i = blockIdx.x * blockDim.x + threadIdx.x;
    if (i < n) {
        int excl = g_incl[i] - g_count[i] + g_partialsEx[i >> 10];
        g_rowStart[i] = excl;
        g_cursor[i]   = excl;
    }
    if (i == 0) g_rowStart[n] = nE;
}

__global__ void reorder_kernel(const int* __restrict__ rows,
                               const int* __restrict__ cols,
                               const float* __restrict__ vals,
                               int nE) {
    int e = blockIdx.x * blockDim.x + threadIdx.x;
    if (e < nE) {
        int r = __ldg(rows + e);
        int p = atomicAdd(&g_cursor[r], 1);
        g_ePacked[p] = make_uint2((unsigned)__ldg(cols + e),
                                  __float_as_uint(__ldg(vals + e)));
    }
}

// ---------------- segmented aggregate: one warp per row, fused ReLU ---------
__global__ __launch_bounds__(512) void aggregate_kernel(const float* __restrict__ HT,
                                                        float* __restrict__ out,
                                                        int nRows) {
    int warp = (blockIdx.x * blockDim.x + threadIdx.x) >> 5;
    int lane = threadIdx.x & 31;
    if (warp >= nRows) return;

    int s    = __ldg(&g_rowStart[warp]);
    int eend = __ldg(&g_rowStart[warp + 1]);

    float4 a0 = make_float4(0.f, 0.f, 0.f, 0.f);
    float4 a1 = make_float4(0.f, 0.f, 0.f, 0.f);

    const float4* HT4 = reinterpret_cast<const float4*>(HT);

    int e = s;
    // 4-edge unrolled main loop: batch 8 independent LDG.128 before any FMA
    for (; e + 4 <= eend; e += 4) {
        uint2 p0 = __ldg(&g_ePacked[e]);
        uint2 p1 = __ldg(&g_ePacked[e + 1]);
        uint2 p2 = __ldg(&g_ePacked[e + 2]);
        uint2 p3 = __ldg(&g_ePacked[e + 3]);
        const float4* r0 = HT4 + (size_t)p0.x * 64;
        const float4* r1 = HT4 + (size_t)p1.x * 64;
        const float4* r2 = HT4 + (size_t)p2.x * 64;
        const float4* r3 = HT4 + (size_t)p3.x * 64;
        float4 x0a = __ldg(&r0[lane]);
        float4 x1a = __ldg(&r1[lane]);
        float4 x2a = __ldg(&r2[lane]);
        float4 x3a = __ldg(&r3[lane]);
        float4 x0b = __ldg(&r0[lane + 32]);
        float4 x1b = __ldg(&r1[lane + 32]);
        float4 x2b = __ldg(&r2[lane + 32]);
        float4 x3b = __ldg(&r3[lane + 32]);
        float v0 = __uint_as_float(p0.y);
        float v1 = __uint_as_float(p1.y);
        float v2 = __uint_as_float(p2.y);
        float v3 = __uint_as_float(p3.y);
        a0.x = fmaf(v0, x0a.x, a0.x); a0.y = fmaf(v0, x0a.y, a0.y);
        a0.z = fmaf(v0, x0a.z, a0.z); a0.w = fmaf(v0, x0a.w, a0.w);
        a1.x = fmaf(v0, x0b.x, a1.x); a1.y = fmaf(v0, x0b.y, a1.y);
        a1.z = fmaf(v0, x0b.z, a1.z); a1.w = fmaf(v0, x0b.w, a1.w);
        a0.x = fmaf(v1, x1a.x, a0.x); a0.y = fmaf(v1, x1a.y, a0.y);
        a0.z = fmaf(v1, x1a.z, a0.z); a0.w = fmaf(v1, x1a.w, a0.w);
        a1.x = fmaf(v1, x1b.x, a1.x); a1.y = fmaf(v1, x1b.y, a1.y);
        a1.z = fmaf(v1, x1b.z, a1.z); a1.w = fmaf(v1, x1b.w, a1.w);
        a0.x = fmaf(v2, x2a.x, a0.x); a0.y = fmaf(v2, x2a.y, a0.y);
        a0.z = fmaf(v2, x2a.z, a0.z); a0.w = fmaf(v2, x2a.w, a0.w);
        a1.x = fmaf(v2, x2b.x, a1.x); a1.y = fmaf(v2, x2b.y, a1.y);
        a1.z = fmaf(v2, x2b.z, a1.z); a1.w = fmaf(v2, x2b.w, a1.w);
        a0.x = fmaf(v3, x3a.x, a0.x); a0.y = fmaf(v3, x3a.y, a0.y);
        a0.z = fmaf(v3, x3a.z, a0.z); a0.w = fmaf(v3, x3a.w, a0.w);
        a1.x = fmaf(v3, x3b.x, a1.x); a1.y = fmaf(v3, x3b.y, a1.y);
        a1.z = fmaf(v3, x3b.z, a1.z); a1.w = fmaf(v3, x3b.w, a1.w);
    }
    for (; e < eend; e++) {
        uint2 p0 = __ldg(&g_ePacked[e]);
        const float4* r0 = HT4 + (size_t)p0.x * 64;
        float4 x0 = __ldg(&r0[lane]);
        float4 x1 = __ldg(&r0[lane + 32]);
        float v0 = __uint_as_float(p0.y);
        a0.x = fmaf(v0, x0.x, a0.x); a0.y = fmaf(v0, x0.y, a0.y);
        a0.z = fmaf(v0, x0.z, a0.z); a0.w = fmaf(v0, x0.w, a0.w);
        a1.x = fmaf(v0, x1.x, a1.x); a1.y = fmaf(v0, x1.y, a1.y);
        a1.z = fmaf(v0, x1.z, a1.z); a1.w = fmaf(v0, x1.w, a1.w);
    }

    // fused ReLU + store (also handles zero-degree rows -> zeros)
    a0.x = fmaxf(a0.x, 0.f); a0.y = fmaxf(a0.y, 0.f);
    a0.z = fmaxf(a0.z, 0.f); a0.w = fmaxf(a0.w, 0.f);
    a1.x = fmaxf(a1.x, 0.f); a1.y = fmaxf(a1.y, 0.f);
    a1.z = fmaxf(a1.z, 0.f); a1.w = fmaxf(a1.w, 0.f);

    float4* out4 = reinterpret_cast<float4*>(out);
    out4[(size_t)warp * 64 + lane]      = a0;
    out4[(size_t)warp * 64 + lane + 32] = a1;
}

// ---------------- launch ----------------------------------------------------
extern "C" void kernel_launch(void* const* d_in, const int* in_sizes, int n_in,
                              void* d_out, int out_size) {
    const float* x       = (const float*)d_in[0];
    const int*   adjRows = (const int*)  d_in[1];
    const int*   adjCols = (const int*)  d_in[2];
    const float* adjVals = (const float*)d_in[3];
    const float* Wk      = (const float*)d_in[4];
    const float* bias    = (const float*)d_in[5];
    const float* cTheta  = (const float*)d_in[6];
    float* out = (float*)d_out;

    const int nNodes = in_sizes[0] / DIM;   // 100000
    const int nE     = in_sizes[1];         // 3200000

    float* htPtr;   cudaGetSymbolAddress((void**)&htPtr, g_htan);

    // constants + hyperbolic bias
    prep_kernel<<<1, 256>>>(bias, cTheta);

    // CSR build (independent of GEMM; single stream serializes fine)
    zero_count_kernel<<<(nNodes + 255) / 256, 256>>>(nNodes);
    hist_kernel<<<(nE + 255) / 256, 256>>>(adjRows, nE);
    scan1_kernel<<<(nNodes + SCAN_T - 1) / SCAN_T, SCAN_T>>>(nNodes);
    scan2_kernel<<<1, 32>>>((nNodes + SCAN_T - 1) / SCAN_T);
    scan3_kernel<<<(nNodes + 255) / 256, 256>>>(nNodes, nE);
    reorder_kernel<<<(nE + 255) / 256, 256>>>(adjRows, adjCols, adjVals, nE);

    // fused GEMM + hyperbolic pointwise -> h_tan
    gemm_fused_kernel<<<(nNodes + 63) / 64, 256>>>(x, Wk, htPtr, nNodes);

    // segmented gather-aggregate with fused ReLU
    aggregate_kernel<<<(nNodes * 32 + 511) / 512, 512>>>(htPtr, out, nNodes);
}

// round 8
// speedup vs baseline: 2.0555x; 1.0019x over previous
#include <cuda_runtime.h>
#include <cuda_bf16.h>
#include <math.h>

#define EPSV 1e-5f
#define NNODES 100000
#define NEDGES 3200000
#define DIM 256
#define SCAN_T 1024
#define SCAN_BLOCKS ((NNODES + SCAN_T - 1) / SCAN_T)   // 98

// ---------------- scratch (device globals; no runtime allocation) ----------
__device__ float g_htan[(size_t)NNODES * DIM];   // tangent-space features
__device__ float g_bhyp[DIM];                    // exp_map_0(bias)
__device__ float g_scal[4];                      // c, sqrt_c, ||b_hyp||^2
__device__ int   g_count[NNODES];                // per-row edge counts
__device__ int   g_incl[NNODES];                 // inclusive per-block scans
__device__ int   g_partials[SCAN_BLOCKS];        // block totals
__device__ int   g_partialsEx[SCAN_BLOCKS];      // exclusive-scanned totals
__device__ int   g_rowStart[NNODES + 1];         // CSR row offsets
__device__ int   g_cursor[NNODES];               // fill cursors
__device__ uint2 g_ePacked[NEDGES];              // {col, bits(val)} reordered

// packed f32x2 FMA: d = a*b + d  (each half is exact fp32 FMA)
#define FMA2(d, a, b) \
    asm("fma.rn.f32x2 %0, %1, %2, %0;" : "+l"(d) : "l"(a), "l"(b))
#define PACK_DUP(d, x) \
    asm("mov.b64 %0, {%1, %1};" : "=l"(d) : "r"(x))
#define UNPACK2(lo, hi, in) \
    asm("mov.b64 {%0, %1}, %2;" : "=f"(lo), "=f"(hi) : "l"(in))

// ---------------- prep (block 0) + zero counts (all blocks) -----------------
__global__ void prep_zero_kernel(const float* __restrict__ bias,
                                 const float* __restrict__ c_theta,
                                 int n) {
    int i = blockIdx.x * blockDim.x + threadIdx.x;
    if (i < n) g_count[i] = 0;

    if (blockIdx.x == 0) {
        __shared__ float red[256];
        int tid = threadIdx.x;
        float b = bias[tid];
        red[tid] = b * b;
        __syncthreads();
        for (int s = 128; s > 0; s >>= 1) {
            if (tid < s) red[tid] += red[tid + s];
            __syncthreads();
        }
        float bb_bias = red[0];

        float ct = c_theta[0];
        float c  = log1pf(expf(ct));        // softplus
        float sc = sqrtf(c);

        float nn = fmaxf(sqrtf(bb_bias), EPSV);
        float f  = tanhf(sc * nn) / (sc * nn);
        g_bhyp[tid] = f * b;
        if (tid == 0) {
            g_scal[0] = c;
            g_scal[1] = sc;
            g_scal[2] = f * f * bb_bias;    // ||b_hyp||^2
        }
    }
}

// ---------------- CSR histogram + scans -------------------------------------
__global__ void hist_kernel(const int* __restrict__ rows, int nE) {
    int e = blockIdx.x * blockDim.x + threadIdx.x;
    if (e < nE) atomicAdd(&g_count[rows[e]], 1);
}

__global__ __launch_bounds__(SCAN_T) void scan1_kernel(int n) {
    __shared__ int s[SCAN_T];
    int t = threadIdx.x;
    int i = blockIdx.x * SCAN_T + t;
    int v = (i < n) ? g_count[i] : 0;
    s[t] = v;
    __syncthreads();
#pragma unroll
    for (int off = 1; off < SCAN_T; off <<= 1) {
        int add = (t >= off) ? s[t - off] : 0;
        __syncthreads();
        s[t] += add;
        __syncthreads();
    }
    if (i < n) g_incl[i] = s[t];
    if (t == SCAN_T - 1) g_partials[blockIdx.x] = s[t];
}

__global__ void scan2_kernel(int nBlocks) {
    if (threadIdx.x == 0 && blockIdx.x == 0) {
        int run = 0;
        for (int b = 0; b < nBlocks; b++) {
            int t = g_partials[b];
            g_partialsEx[b] = run;
            run += t;
        }
    }
}

__global__ void scan3_kernel(int n, int nE) {
    int i = blockIdx.x * blockDim.x + threadIdx.x;
    if (i < n) {
        int excl = g_incl[i] - g_count[i] + g_partialsEx[i >> 10];
        g_rowStart[i] = excl;
        g_cursor[i]   = excl;
    }
    if (i == 0) g_rowStart[n] = nE;
}

__global__ void reorder_kernel(const int* __restrict__ rows,
                               const int* __restrict__ cols,
                               const float* __restrict__ vals,
                               int nE) {
    int e = blockIdx.x * blockDim.x + threadIdx.x;
    if (e < nE) {
        int r = __ldg(rows + e);
        int p = atomicAdd(&g_cursor[r], 1);
        g_ePacked[p] = make_uint2((unsigned)__ldg(cols + e),
                                  __float_as_uint(__ldg(vals + e)));
    }
}

// ---------------- fused SGEMM + hyperbolic pointwise ------------------------
// tile 64 rows x 256 cols, BK=16, 256 threads, 8x8 microtile.
// Inner product via packed fma.rn.f32x2 (column pairs), double-buffered smem.
__global__ __launch_bounds__(256, 2) void gemm_fused_kernel(
        const float* __restrict__ X,
        const float* __restrict__ W,
        float* __restrict__ HT,
        int nrows) {
    __shared__ __align__(16) float As[2][16][64];    // As[buf][k][m]
    __shared__ __align__(16) float Bs[2][16][256];   // Bs[buf][k][n]

    const int tid = threadIdx.x;
    const int tx = tid & 31;
    const int ty = tid >> 5;
    const int rowBase = blockIdx.x * 64;

    const int ar = tid >> 2;
    const int aq = tid & 3;
    const int agrow = rowBase + ar;

    unsigned long long acc2[8][4];
#pragma unroll
    for (int i = 0; i < 8; i++)
#pragma unroll
        for (int p = 0; p < 4; p++) acc2[i][p] = 0ull;

    {
        float4 va = make_float4(0.f, 0.f, 0.f, 0.f);
        if (agrow < nrows)
            va = *reinterpret_cast<const float4*>(X + (size_t)agrow * 256 + aq * 4);
        As[0][aq * 4 + 0][ar] = va.x;
        As[0][aq * 4 + 1][ar] = va.y;
        As[0][aq * 4 + 2][ar] = va.z;
        As[0][aq * 4 + 3][ar] = va.w;
#pragma unroll
        for (int i = 0; i < 4; i++) {
            int idx = tid + i * 256;
            int kr  = idx >> 6;
            int cq  = idx & 63;
            float4 v = *reinterpret_cast<const float4*>(W + (size_t)kr * 256 + cq * 4);
            *reinterpret_cast<float4*>(&Bs[0][kr][cq * 4]) = v;
        }
    }
    __syncthreads();

#pragma unroll 1
    for (int t = 0; t < 16; t++) {
        const int cur = t & 1;
        const int nxt = cur ^ 1;

        float4 na = make_float4(0.f, 0.f, 0.f, 0.f);
        float4 nb[4];
        if (t < 15) {
            int k0n = (t + 1) * 16;
            if (agrow < nrows)
                na = *reinterpret_cast<const float4*>(X + (size_t)agrow * 256 + k0n + aq * 4);
#pragma unroll
            for (int i = 0; i < 4; i++) {
                int idx = tid + i * 256;
                int kr  = idx >> 6;
                int cq  = idx & 63;
                nb[i] = *reinterpret_cast<const float4*>(W + (size_t)(k0n + kr) * 256 + cq * 4);
            }
        }

#pragma unroll
        for (int k = 0; k < 16; k++) {
            float4 a0 = *reinterpret_cast<const float4*>(&As[cur][k][ty * 8]);
            float4 a1 = *reinterpret_cast<const float4*>(&As[cur][k][ty * 8 + 4]);
            ulonglong2 q0 = *reinterpret_cast<const ulonglong2*>(&Bs[cur][k][tx * 8]);
            ulonglong2 q1 = *reinterpret_cast<const ulonglong2*>(&Bs[cur][k][tx * 8 + 4]);

            float a[8];
            a[0]=a0.x; a[1]=a0.y; a[2]=a0.z; a[3]=a0.w;
            a[4]=a1.x; a[5]=a1.y; a[6]=a1.z; a[7]=a1.w;
#pragma unroll
            for (int i = 0; i < 8; i++) {
                unsigned long long ap;
                PACK_DUP(ap, __float_as_uint(a[i]));
                FMA2(acc2[i][0], ap, q0.x);
                FMA2(acc2[i][1], ap, q0.y);
                FMA2(acc2[i][2], ap, q1.x);
                FMA2(acc2[i][3], ap, q1.y);
            }
        }

        if (t < 15) {
            As[nxt][aq * 4 + 0][ar] = na.x;
            As[nxt][aq * 4 + 1][ar] = na.y;
            As[nxt][aq * 4 + 2][ar] = na.z;
            As[nxt][aq * 4 + 3][ar] = na.w;
#pragma unroll
            for (int i = 0; i < 4; i++) {
                int idx = tid + i * 256;
                int kr  = idx >> 6;
                int cq  = idx & 63;
                *reinterpret_cast<float4*>(&Bs[nxt][kr][cq * 4]) = nb[i];
            }
        }
        __syncthreads();
    }

    float acc[8][8];
#pragma unroll
    for (int i = 0; i < 8; i++)
#pragma unroll
        for (int p = 0; p < 4; p++)
            UNPACK2(acc[i][2 * p], acc[i][2 * p + 1], acc2[i][p]);

    // ---- fused hyperbolic epilogue ----
    float bh[8];
    {
        float4 h0 = *reinterpret_cast<const float4*>(g_bhyp + tx * 8);
        float4 h1 = *reinterpret_cast<const float4*>(g_bhyp + tx * 8 + 4);
        bh[0]=h0.x; bh[1]=h0.y; bh[2]=h0.z; bh[3]=h0.w;
        bh[4]=h1.x; bh[5]=h1.y; bh[6]=h1.z; bh[7]=h1.w;
    }
    float c   = g_scal[0];
    float sc  = g_scal[1];
    float bbh = g_scal[2];

#pragma unroll
    for (int i = 0; i < 8; i++) {
        float zz = 0.f, zb = 0.f;
#pragma unroll
        for (int j = 0; j < 8; j++) {
            zz = fmaf(acc[i][j], acc[i][j], zz);
            zb = fmaf(acc[i][j], bh[j], zb);
        }
#pragma unroll
        for (int off = 16; off > 0; off >>= 1) {
            zz += __shfl_xor_sync(0xFFFFFFFFu, zz, off);
            zb += __shfl_xor_sync(0xFFFFFFFFu, zb, off);
        }

        float nz = fmaxf(sqrtf(zz), EPSV);
        float f1 = tanhf(sc * nz) / (sc * nz);

        float ab = f1 * zb;
        float aa = f1 * f1 * zz;

        float t2    = 1.0f + 2.0f * c * ab;
        float alpha = t2 + c * bbh;
        float beta  = 1.0f - c * aa;
        float den   = fmaxf(t2 + c * c * aa * bbh, EPSV);

        float hh = (alpha * alpha * aa + 2.0f * alpha * beta * ab + beta * beta * bbh)
                   / (den * den);

        float npr   = fmaxf(sqrtf(hh), EPSV);
        float maxn  = (1.0f - EPSV) / sc;
        float scale = (npr > maxn) ? (maxn / npr) : 1.0f;

        float ny  = fmaxf(scale * sqrtf(hh), EPSV);
        float arg = fminf(sc * ny, 1.0f - EPSV);
        float fac = atanhf(arg) / (sc * ny);

        float cA = fac * scale * alpha * f1 / den;
        float cB = fac * scale * beta / den;

        int row = rowBase + ty * 8 + i;
        if (row < nrows) {
            float4 o0 = make_float4(fmaf(cA, acc[i][0], cB * bh[0]),
                                    fmaf(cA, acc[i][1], cB * bh[1]),
                                    fmaf(cA, acc[i][2], cB * bh[2]),
                                    fmaf(cA, acc[i][3], cB * bh[3]));
            float4 o1 = make_float4(fmaf(cA, acc[i][4], cB * bh[4]),
                                    fmaf(cA, acc[i][5], cB * bh[5]),
                                    fmaf(cA, acc[i][6], cB * bh[6]),
                                    fmaf(cA, acc[i][7], cB * bh[7]));
            float* orow = HT + (size_t)row * 256;
            *reinterpret_cast<float4*>(orow + tx * 8)     = o0;
            *reinterpret_cast<float4*>(orow + tx * 8 + 4) = o1;
        }
    }
}

// ---------------- segmented aggregate: one warp per row, fused ReLU ---------
__global__ __launch_bounds__(512) void aggregate_kernel(const float* __restrict__ HT,
                                                        float* __restrict__ out,
                                                        int nRows) {
    int warp = (blockIdx.x * blockDim.x + threadIdx.x) >> 5;
    int lane = threadIdx.x & 31;
    if (warp >= nRows) return;

    int s    = __ldg(&g_rowStart[warp]);
    int eend = __ldg(&g_rowStart[warp + 1]);

    float4 a0 = make_float4(0.f, 0.f, 0.f, 0.f);
    float4 a1 = make_float4(0.f, 0.f, 0.f, 0.f);

    const float4* HT4 = reinterpret_cast<const float4*>(HT);

    int e = s;
    for (; e + 4 <= eend; e += 4) {
        uint2 p0 = __ldg(&g_ePacked[e]);
        uint2 p1 = __ldg(&g_ePacked[e + 1]);
        uint2 p2 = __ldg(&g_ePacked[e + 2]);
        uint2 p3 = __ldg(&g_ePacked[e + 3]);
        const float4* r0 = HT4 + (size_t)p0.x * 64;
        const float4* r1 = HT4 + (size_t)p1.x * 64;
        const float4* r2 = HT4 + (size_t)p2.x * 64;
        const float4* r3 = HT4 + (size_t)p3.x * 64;
        float4 x0a = __ldg(&r0[lane]);
        float4 x1a = __ldg(&r1[lane]);
        float4 x2a = __ldg(&r2[lane]);
        float4 x3a = __ldg(&r3[lane]);
        float4 x0b = __ldg(&r0[lane + 32]);
        float4 x1b = __ldg(&r1[lane + 32]);
        float4 x2b = __ldg(&r2[lane + 32]);
        float4 x3b = __ldg(&r3[lane + 32]);
        float v0 = __uint_as_float(p0.y);
        float v1 = __uint_as_float(p1.y);
        float v2 = __uint_as_float(p2.y);
        float v3 = __uint_as_float(p3.y);
        a0.x = fmaf(v0, x0a.x, a0.x); a0.y = fmaf(v0, x0a.y, a0.y);
        a0.z = fmaf(v0, x0a.z, a0.z); a0.w = fmaf(v0, x0a.w, a0.w);
        a1.x = fmaf(v0, x0b.x, a1.x); a1.y = fmaf(v0, x0b.y, a1.y);
        a1.z = fmaf(v0, x0b.z, a1.z); a1.w = fmaf(v0, x0b.w, a1.w);
        a0.x = fmaf(v1, x1a.x, a0.x); a0.y = fmaf(v1, x1a.y, a0.y);
        a0.z = fmaf(v1, x1a.z, a0.z); a0.w = fmaf(v1, x1a.w, a0.w);
        a1.x = fmaf(v1, x1b.x, a1.x); a1.y = fmaf(v1, x1b.y, a1.y);
        a1.z = fmaf(v1, x1b.z, a1.z); a1.w = fmaf(v1, x1b.w, a1.w);
        a0.x = fmaf(v2, x2a.x, a0.x); a0.y = fmaf(v2, x2a.y, a0.y);
        a0.z = fmaf(v2, x2a.z, a0.z); a0.w = fmaf(v2, x2a.w, a0.w);
        a1.x = fmaf(v2, x2b.x, a1.x); a1.y = fmaf(v2, x2b.y, a1.y);
        a1.z = fmaf(v2, x2b.z, a1.z); a1.w = fmaf(v2, x2b.w, a1.w);
        a0.x = fmaf(v3, x3a.x, a0.x); a0.y = fmaf(v3, x3a.y, a0.y);
        a0.z = fmaf(v3, x3a.z, a0.z); a0.w = fmaf(v3, x3a.w, a0.w);
        a1.x = fmaf(v3, x3b.x, a1.x); a1.y = fmaf(v3, x3b.y, a1.y);
        a1.z = fmaf(v3, x3b.z, a1.z); a1.w = fmaf(v3, x3b.w, a1.w);
    }
    for (; e < eend; e++) {
        uint2 p0 = __ldg(&g_ePacked[e]);
        const float4* r0 = HT4 + (size_t)p0.x * 64;
        float4 x0 = __ldg(&r0[lane]);
        float4 x1 = __ldg(&r0[lane + 32]);
        float v0 = __uint_as_float(p0.y);
        a0.x = fmaf(v0, x0.x, a0.x); a0.y = fmaf(v0, x0.y, a0.y);
        a0.z = fmaf(v0, x0.z, a0.z); a0.w = fmaf(v0, x0.w, a0.w);
        a1.x = fmaf(v0, x1.x, a1.x); a1.y = fmaf(v0, x1.y, a1.y);
        a1.z = fmaf(v0, x1.z, a1.z); a1.w = fmaf(v0, x1.w, a1.w);
    }

    a0.x = fmaxf(a0.x, 0.f); a0.y = fmaxf(a0.y, 0.f);
    a0.z = fmaxf(a0.z, 0.f); a0.w = fmaxf(a0.w, 0.f);
    a1.x = fmaxf(a1.x, 0.f); a1.y = fmaxf(a1.y, 0.f);
    a1.z = fmaxf(a1.z, 0.f); a1.w = fmaxf(a1.w, 0.f);

    float4* out4 = reinterpret_cast<float4*>(out);
    out4[(size_t)warp * 64 + lane]      = a0;
    out4[(size_t)warp * 64 + lane + 32] = a1;
}

// ---------------- launch ----------------------------------------------------
extern "C" void kernel_launch(void* const* d_in, const int* in_sizes, int n_in,
                              void* d_out, int out_size) {
    const float* x       = (const float*)d_in[0];
    const int*   adjRows = (const int*)  d_in[1];
    const int*   adjCols = (const int*)  d_in[2];
    const float* adjVals = (const float*)d_in[3];
    const float* Wk      = (const float*)d_in[4];
    const float* bias    = (const float*)d_in[5];
    const float* cTheta  = (const float*)d_in[6];
    float* out = (float*)d_out;

    const int nNodes = in_sizes[0] / DIM;   // 100000
    const int nE     = in_sizes[1];         // 3200000

    float* htPtr;   cudaGetSymbolAddress((void**)&htPtr, g_htan);

    // 1: prep (block 0) + zero counts
    prep_zero_kernel<<<(nNodes + 255) / 256, 256>>>(bias, cTheta, nNodes);

    // 2-3: CSR histogram + first scan
    hist_kernel<<<(nE + 255) / 256, 256>>>(adjRows, nE);
    scan1_kernel<<<(nNodes + SCAN_T - 1) / SCAN_T, SCAN_T>>>(nNodes);

    // 4: fused GEMM + hyperbolic pointwise (placed 4th so ncu profiles it)
    gemm_fused_kernel<<<(nNodes + 63) / 64, 256>>>(x, Wk, htPtr, nNodes);

    // 5-7: finish CSR build
    scan2_kernel<<<1, 32>>>((nNodes + SCAN_T - 1) / SCAN_T);
    scan3_kernel<<<(nNodes + 255) / 256, 256>>>(nNodes, nE);
    reorder_kernel<<<(nE + 255) / 256, 256>>>(adjRows, adjCols, adjVals, nE);

    // 8: segmented gather-aggregate with fused ReLU
    aggregate_kernel<<<(nNodes * 32 + 511) / 512, 512>>>(htPtr, out, nNodes);
}

// round 9
// speedup vs baseline: 2.5404x; 1.2359x over previous
#include <cuda_runtime.h>
#include <cuda_bf16.h>
#include <cuda_fp16.h>
#include <math.h>

#define EPSV 1e-5f
#define NNODES 100000
#define NEDGES 3200000
#define DIM 256
#define SCAN_T 1024
#define SCAN_BLOCKS ((NNODES + SCAN_T - 1) / SCAN_T)   // 98

// ---------------- scratch (device globals; no runtime allocation) ----------
__device__ __half g_htan[(size_t)NNODES * DIM];  // tangent-space features (fp16)
__device__ float  g_bhyp[DIM];                   // exp_map_0(bias)
__device__ float  g_scal[4];                     // c, sqrt_c, ||b_hyp||^2
__device__ int    g_count[NNODES];               // per-row edge counts
__device__ int    g_incl[NNODES];                // inclusive per-block scans
__device__ int    g_partials[SCAN_BLOCKS];       // block totals
__device__ int    g_partialsEx[SCAN_BLOCKS];     // exclusive-scanned totals
__device__ int    g_rowStart[NNODES + 1];        // CSR row offsets
__device__ int    g_cursor[NNODES];              // fill cursors
__device__ uint2  g_ePacked[NEDGES];             // {col, bits(val)} reordered

// packed f32x2 FMA: d = a*b + d  (each half is exact fp32 FMA)
#define FMA2(d, a, b) \
    asm("fma.rn.f32x2 %0, %1, %2, %0;" : "+l"(d) : "l"(a), "l"(b))
#define PACK_DUP(d, x) \
    asm("mov.b64 %0, {%1, %1};" : "=l"(d) : "r"(x))
#define UNPACK2(lo, hi, in) \
    asm("mov.b64 {%0, %1}, %2;" : "=f"(lo), "=f"(hi) : "l"(in))

// ---------------- prep (block 0) + zero counts (all blocks) -----------------
__global__ void prep_zero_kernel(const float* __restrict__ bias,
                                 const float* __restrict__ c_theta,
                                 int n) {
    int i = blockIdx.x * blockDim.x + threadIdx.x;
    if (i < n) g_count[i] = 0;

    if (blockIdx.x == 0) {
        __shared__ float red[256];
        int tid = threadIdx.x;
        float b = bias[tid];
        red[tid] = b * b;
        __syncthreads();
        for (int s = 128; s > 0; s >>= 1) {
            if (tid < s) red[tid] += red[tid + s];
            __syncthreads();
        }
        float bb_bias = red[0];

        float ct = c_theta[0];
        float c  = log1pf(expf(ct));        // softplus
        float sc = sqrtf(c);

        float nn = fmaxf(sqrtf(bb_bias), EPSV);
        float f  = tanhf(sc * nn) / (sc * nn);
        g_bhyp[tid] = f * b;
        if (tid == 0) {
            g_scal[0] = c;
            g_scal[1] = sc;
            g_scal[2] = f * f * bb_bias;    // ||b_hyp||^2
        }
    }
}

// ---------------- CSR histogram + scans -------------------------------------
__global__ void hist_kernel(const int* __restrict__ rows, int nE) {
    int e = blockIdx.x * blockDim.x + threadIdx.x;
    if (e < nE) atomicAdd(&g_count[rows[e]], 1);
}

__global__ __launch_bounds__(SCAN_T) void scan1_kernel(int n) {
    __shared__ int s[SCAN_T];
    int t = threadIdx.x;
    int i = blockIdx.x * SCAN_T + t;
    int v = (i < n) ? g_count[i] : 0;
    s[t] = v;
    __syncthreads();
#pragma unroll
    for (int off = 1; off < SCAN_T; off <<= 1) {
        int add = (t >= off) ? s[t - off] : 0;
        __syncthreads();
        s[t] += add;
        __syncthreads();
    }
    if (i < n) g_incl[i] = s[t];
    if (t == SCAN_T - 1) g_partials[blockIdx.x] = s[t];
}

__global__ void scan2_kernel(int nBlocks) {
    if (threadIdx.x == 0 && blockIdx.x == 0) {
        int run = 0;
        for (int b = 0; b < nBlocks; b++) {
            int t = g_partials[b];
            g_partialsEx[b] = run;
            run += t;
        }
    }
}

__global__ void scan3_kernel(int n, int nE) {
    int i = blockIdx.x * blockDim.x + threadIdx.x;
    if (i < n) {
        int excl = g_incl[i] - g_count[i] + g_partialsEx[i >> 10];
        g_rowStart[i] = excl;
        g_cursor[i]   = excl;
    }
    if (i == 0) g_rowStart[n] = nE;
}

__global__ void reorder_kernel(const int* __restrict__ rows,
                               const int* __restrict__ cols,
                               const float* __restrict__ vals,
                               int nE) {
    int e = blockIdx.x * blockDim.x + threadIdx.x;
    if (e < nE) {
        int r = __ldg(rows + e);
        int p = atomicAdd(&g_cursor[r], 1);
        g_ePacked[p] = make_uint2((unsigned)__ldg(cols + e),
                                  __float_as_uint(__ldg(vals + e)));
    }
}

// ---------------- fused SGEMM + hyperbolic pointwise (fp16 output) ----------
// tile 64 rows x 256 cols, BK=16, 256 threads, 8x8 microtile.
// Inner product via packed fma.rn.f32x2 (column pairs), double-buffered smem.
__global__ __launch_bounds__(256, 2) void gemm_fused_kernel(
        const float* __restrict__ X,
        const float* __restrict__ W,
        __half* __restrict__ HT,
        int nrows) {
    __shared__ __align__(16) float As[2][16][64];    // As[buf][k][m]
    __shared__ __align__(16) float Bs[2][16][256];   // Bs[buf][k][n]

    const int tid = threadIdx.x;
    const int tx = tid & 31;
    const int ty = tid >> 5;
    const int rowBase = blockIdx.x * 64;

    const int ar = tid >> 2;
    const int aq = tid & 3;
    const int agrow = rowBase + ar;

    unsigned long long acc2[8][4];
#pragma unroll
    for (int i = 0; i < 8; i++)
#pragma unroll
        for (int p = 0; p < 4; p++) acc2[i][p] = 0ull;

    {
        float4 va = make_float4(0.f, 0.f, 0.f, 0.f);
        if (agrow < nrows)
            va = *reinterpret_cast<const float4*>(X + (size_t)agrow * 256 + aq * 4);
        As[0][aq * 4 + 0][ar] = va.x;
        As[0][aq * 4 + 1][ar] = va.y;
        As[0][aq * 4 + 2][ar] = va.z;
        As[0][aq * 4 + 3][ar] = va.w;
#pragma unroll
        for (int i = 0; i < 4; i++) {
            int idx = tid + i * 256;
            int kr  = idx >> 6;
            int cq  = idx & 63;
            float4 v = *reinterpret_cast<const float4*>(W + (size_t)kr * 256 + cq * 4);
            *reinterpret_cast<float4*>(&Bs[0][kr][cq * 4]) = v;
        }
    }
    __syncthreads();

#pragma unroll 1
    for (int t = 0; t < 16; t++) {
        const int cur = t & 1;
        const int nxt = cur ^ 1;

        float4 na = make_float4(0.f, 0.f, 0.f, 0.f);
        float4 nb[4];
        if (t < 15) {
            int k0n = (t + 1) * 16;
            if (agrow < nrows)
                na = *reinterpret_cast<const float4*>(X + (size_t)agrow * 256 + k0n + aq * 4);
#pragma unroll
            for (int i = 0; i < 4; i++) {
                int idx = tid + i * 256;
                int kr  = idx >> 6;
                int cq  = idx & 63;
                nb[i] = *reinterpret_cast<const float4*>(W + (size_t)(k0n + kr) * 256 + cq * 4);
            }
        }

#pragma unroll
        for (int k = 0; k < 16; k++) {
            float4 a0 = *reinterpret_cast<const float4*>(&As[cur][k][ty * 8]);
            float4 a1 = *reinterpret_cast<const float4*>(&As[cur][k][ty * 8 + 4]);
            ulonglong2 q0 = *reinterpret_cast<const ulonglong2*>(&Bs[cur][k][tx * 8]);
            ulonglong2 q1 = *reinterpret_cast<const ulonglong2*>(&Bs[cur][k][tx * 8 + 4]);

            float a[8];
            a[0]=a0.x; a[1]=a0.y; a[2]=a0.z; a[3]=a0.w;
            a[4]=a1.x; a[5]=a1.y; a[6]=a1.z; a[7]=a1.w;
#pragma unroll
            for (int i = 0; i < 8; i++) {
                unsigned long long ap;
                PACK_DUP(ap, __float_as_uint(a[i]));
                FMA2(acc2[i][0], ap, q0.x);
                FMA2(acc2[i][1], ap, q0.y);
                FMA2(acc2[i][2], ap, q1.x);
                FMA2(acc2[i][3], ap, q1.y);
            }
        }

        if (t < 15) {
            As[nxt][aq * 4 + 0][ar] = na.x;
            As[nxt][aq * 4 + 1][ar] = na.y;
            As[nxt][aq * 4 + 2][ar] = na.z;
            As[nxt][aq * 4 + 3][ar] = na.w;
#pragma unroll
            for (int i = 0; i < 4; i++) {
                int idx = tid + i * 256;
                int kr  = idx >> 6;
                int cq  = idx & 63;
                *reinterpret_cast<float4*>(&Bs[nxt][kr][cq * 4]) = nb[i];
            }
        }
        __syncthreads();
    }

    float acc[8][8];
#pragma unroll
    for (int i = 0; i < 8; i++)
#pragma unroll
        for (int p = 0; p < 4; p++)
            UNPACK2(acc[i][2 * p], acc[i][2 * p + 1], acc2[i][p]);

    // ---- fused hyperbolic epilogue ----
    float bh[8];
    {
        float4 h0 = *reinterpret_cast<const float4*>(g_bhyp + tx * 8);
        float4 h1 = *reinterpret_cast<const float4*>(g_bhyp + tx * 8 + 4);
        bh[0]=h0.x; bh[1]=h0.y; bh[2]=h0.z; bh[3]=h0.w;
        bh[4]=h1.x; bh[5]=h1.y; bh[6]=h1.z; bh[7]=h1.w;
    }
    float c   = g_scal[0];
    float sc  = g_scal[1];
    float bbh = g_scal[2];

#pragma unroll
    for (int i = 0; i < 8; i++) {
        float zz = 0.f, zb = 0.f;
#pragma unroll
        for (int j = 0; j < 8; j++) {
            zz = fmaf(acc[i][j], acc[i][j], zz);
            zb = fmaf(acc[i][j], bh[j], zb);
        }
#pragma unroll
        for (int off = 16; off > 0; off >>= 1) {
            zz += __shfl_xor_sync(0xFFFFFFFFu, zz, off);
            zb += __shfl_xor_sync(0xFFFFFFFFu, zb, off);
        }

        float nz = fmaxf(sqrtf(zz), EPSV);
        float f1 = tanhf(sc * nz) / (sc * nz);

        float ab = f1 * zb;
        float aa = f1 * f1 * zz;

        float t2    = 1.0f + 2.0f * c * ab;
        float alpha = t2 + c * bbh;
        float beta  = 1.0f - c * aa;
        float den   = fmaxf(t2 + c * c * aa * bbh, EPSV);

        float hh = (alpha * alpha * aa + 2.0f * alpha * beta * ab + beta * beta * bbh)
                   / (den * den);

        float npr   = fmaxf(sqrtf(hh), EPSV);
        float maxn  = (1.0f - EPSV) / sc;
        float scale = (npr > maxn) ? (maxn / npr) : 1.0f;

        float ny  = fmaxf(scale * sqrtf(hh), EPSV);
        float arg = fminf(sc * ny, 1.0f - EPSV);
        float fac = atanhf(arg) / (sc * ny);

        float cA = fac * scale * alpha * f1 / den;
        float cB = fac * scale * beta / den;

        int row = rowBase + ty * 8 + i;
        if (row < nrows) {
            // convert 8 outputs to fp16, one 16B store per lane
            __half2 hv[4];
            hv[0] = __float22half2_rn(make_float2(fmaf(cA, acc[i][0], cB * bh[0]),
                                                  fmaf(cA, acc[i][1], cB * bh[1])));
            hv[1] = __float22half2_rn(make_float2(fmaf(cA, acc[i][2], cB * bh[2]),
                                                  fmaf(cA, acc[i][3], cB * bh[3])));
            hv[2] = __float22half2_rn(make_float2(fmaf(cA, acc[i][4], cB * bh[4]),
                                                  fmaf(cA, acc[i][5], cB * bh[5])));
            hv[3] = __float22half2_rn(make_float2(fmaf(cA, acc[i][6], cB * bh[6]),
                                                  fmaf(cA, acc[i][7], cB * bh[7])));
            *reinterpret_cast<uint4*>(HT + (size_t)row * 256 + tx * 8) =
                *reinterpret_cast<const uint4*>(hv);
        }
    }
}

// ---------------- segmented aggregate (fp16 gather), fused ReLU -------------
// One warp per row; each lane owns 8 columns (lane*8 .. lane*8+7).
__global__ __launch_bounds__(512) void aggregate_kernel(const __half* __restrict__ HT,
                                                        float* __restrict__ out,
                                                        int nRows) {
    int warp = (blockIdx.x * blockDim.x + threadIdx.x) >> 5;
    int lane = threadIdx.x & 31;
    if (warp >= nRows) return;

    int s    = __ldg(&g_rowStart[warp]);
    int eend = __ldg(&g_rowStart[warp + 1]);

    float acc[8];
#pragma unroll
    for (int q = 0; q < 8; q++) acc[q] = 0.f;

    int e = s;
    // 8-edge unrolled main loop: 8 independent LDG.128 in flight
    for (; e + 8 <= eend; e += 8) {
        uint2 p[8];
#pragma unroll
        for (int j = 0; j < 8; j++) p[j] = __ldg(&g_ePacked[e + j]);
        uint4 d[8];
#pragma unroll
        for (int j = 0; j < 8; j++) {
            const uint4* src = reinterpret_cast<const uint4*>(HT + (size_t)p[j].x * 256);
            d[j] = __ldg(src + lane);
        }
#pragma unroll
        for (int j = 0; j < 8; j++) {
            float v = __uint_as_float(p[j].y);
            const __half2* hp = reinterpret_cast<const __half2*>(&d[j]);
#pragma unroll
            for (int q = 0; q < 4; q++) {
                float2 f = __half22float2(hp[q]);
                acc[2 * q]     = fmaf(v, f.x, acc[2 * q]);
                acc[2 * q + 1] = fmaf(v, f.y, acc[2 * q + 1]);
            }
        }
    }
    for (; e < eend; e++) {
        uint2 p0 = __ldg(&g_ePacked[e]);
        const uint4* src = reinterpret_cast<const uint4*>(HT + (size_t)p0.x * 256);
        uint4 d0 = __ldg(src + lane);
        float v = __uint_as_float(p0.y);
        const __half2* hp = reinterpret_cast<const __half2*>(&d0);
#pragma unroll
        for (int q = 0; q < 4; q++) {
            float2 f = __half22float2(hp[q]);
            acc[2 * q]     = fmaf(v, f.x, acc[2 * q]);
            acc[2 * q + 1] = fmaf(v, f.y, acc[2 * q + 1]);
        }
    }

    // fused ReLU + store (zero-degree rows -> zeros)
    float4 o0 = make_float4(fmaxf(acc[0], 0.f), fmaxf(acc[1], 0.f),
                            fmaxf(acc[2], 0.f), fmaxf(acc[3], 0.f));
    float4 o1 = make_float4(fmaxf(acc[4], 0.f), fmaxf(acc[5], 0.f),
                            fmaxf(acc[6], 0.f), fmaxf(acc[7], 0.f));
    float4* outp = reinterpret_cast<float4*>(out + (size_t)warp * 256 + lane * 8);
    outp[0] = o0;
    outp[1] = o1;
}

// ---------------- launch ----------------------------------------------------
extern "C" void kernel_launch(void* const* d_in, const int* in_sizes, int n_in,
                              void* d_out, int out_size) {
    const float* x       = (const float*)d_in[0];
    const int*   adjRows = (const int*)  d_in[1];
    const int*   adjCols = (const int*)  d_in[2];
    const float* adjVals = (const float*)d_in[3];
    const float* Wk      = (const float*)d_in[4];
    const float* bias    = (const float*)d_in[5];
    const float* cTheta  = (const float*)d_in[6];
    float* out = (float*)d_out;

    const int nNodes = in_sizes[0] / DIM;   // 100000
    const int nE     = in_sizes[1];         // 3200000

    __half* htPtr;  cudaGetSymbolAddress((void**)&htPtr, g_htan);

    // 1: prep (block 0) + zero counts
    prep_zero_kernel<<<(nNodes + 255) / 256, 256>>>(bias, cTheta, nNodes);

    // 2-3: CSR histogram + first scan
    hist_kernel<<<(nE + 255) / 256, 256>>>(adjRows, nE);
    scan1_kernel<<<(nNodes + SCAN_T - 1) / SCAN_T, SCAN_T>>>(nNodes);

    // 4: fused GEMM + hyperbolic pointwise (placed 4th so ncu profiles it)
    gemm_fused_kernel<<<(nNodes + 63) / 64, 256>>>(x, Wk, htPtr, nNodes);

    // 5-7: finish CSR build
    scan2_kernel<<<1, 32>>>((nNodes + SCAN_T - 1) / SCAN_T);
    scan3_kernel<<<(nNodes + 255) / 256, 256>>>(nNodes, nE);
    reorder_kernel<<<(nE + 255) / 256, 256>>>(adjRows, adjCols, adjVals, nE);

    // 8: segmented gather-aggregate (fp16) with fused ReLU
    aggregate_kernel<<<(nNodes * 32 + 511) / 512, 512>>>(htPtr, out, nNodes);
}